// round 5
// baseline (speedup 1.0000x reference)
#include <cuda_runtime.h>
#include <mma.h>
#include <cstdint>
#include <math.h>

using namespace nvcuda;

// Problem constants
#define BATCH 2
#define SEQ   2048
#define SIZE  1024
#define HEADS 16
#define HDIM  64
#define M_TOK (BATCH * SEQ)
#define BH    (BATCH * HEADS)

// -------- scratch (device globals; no allocations allowed) --------
__device__ float g_q[(size_t)BH * SEQ * HDIM];        // [bh, s, d]
__device__ float g_k[(size_t)BH * SEQ * HDIM];        // [bh, s, d]
__device__ float g_v[(size_t)BH * SEQ * HDIM];        // [bh, s, d]
__device__ float g_oh[(size_t)BH * SEQ * HDIM];       // [bh, s, d]
__device__ float g_attn_scratch[(size_t)BH * SEQ * SEQ];
__device__ float g_out_scratch[(size_t)M_TOK * SIZE];

__device__ __forceinline__ float f2tf32f(float x) {
    uint32_t r;
    asm("cvt.rna.tf32.f32 %0, %1;" : "=r"(r) : "f"(x));
    return __uint_as_float(r);
}

// fragment typedefs
typedef wmma::fragment<wmma::matrix_a, 16, 16, 8, wmma::precision::tf32, wmma::row_major> FragA;
typedef wmma::fragment<wmma::matrix_b, 16, 16, 8, wmma::precision::tf32, wmma::col_major> FragBc;
typedef wmma::fragment<wmma::matrix_b, 16, 16, 8, wmma::precision::tf32, wmma::row_major> FragBr;
typedef wmma::fragment<wmma::accumulator, 16, 16, 8, float> FragC;

#define LDA 36   // smem leading dim for 32-wide K tiles (pad 4)
#define LDQ 68   // smem leading dim for 64-wide tiles (pad 4)
#define LDS_ 132 // smem leading dim for 128-wide S tile (pad 4)

// ==================================================================
// Projection GEMM: Y = X @ W^T + bias.  M=4096, N=1024, K=1024.
// ==================================================================
template<int IN_MODE, int OUT_MODE>
__global__ void __launch_bounds__(256) proj_wmma(const float* __restrict__ X,
                                                 const float* __restrict__ W,
                                                 const float* __restrict__ bias,
                                                 float* __restrict__ Y) {
    __shared__ __align__(16) float As[128 * LDA];
    __shared__ __align__(16) float Bs[128 * LDA];
    __shared__ __align__(16) float stage[8][272];

    const int tid = threadIdx.x, wid = tid >> 5, lane = tid & 31;
    const int bm = blockIdx.y, bn = blockIdx.x;
    const int wm0 = (wid & 1) * 64, wn0 = (wid >> 1) * 32;

    FragC acc[4][2];
    #pragma unroll
    for (int mt = 0; mt < 4; mt++)
        #pragma unroll
        for (int nt = 0; nt < 2; nt++) wmma::fill_fragment(acc[mt][nt], 0.0f);

    for (int kc = 0; kc < 1024; kc += 32) {
        #pragma unroll
        for (int l = 0; l < 4; l++) {
            int v = tid + l * 256;
            int i = v >> 3;
            int j = (v & 7) * 4;
            float4 t;
            if (IN_MODE == 0) {
                t = *reinterpret_cast<const float4*>(
                    X + (size_t)(bm * 128 + i) * 1024 + kc + j);
            } else {
                int gm = bm * 128 + i;
                int b = gm >> 11, s = gm & 2047;
                int h = kc >> 6, d0 = kc & 63;
                t = *reinterpret_cast<const float4*>(
                    X + ((((size_t)b * HEADS + h) * SEQ + s) << 6) + d0 + j);
            }
            float4 u = {f2tf32f(t.x), f2tf32f(t.y), f2tf32f(t.z), f2tf32f(t.w)};
            *reinterpret_cast<float4*>(&As[i * LDA + j]) = u;
            float4 w = *reinterpret_cast<const float4*>(
                W + (size_t)(bn * 128 + i) * 1024 + kc + j);
            float4 uw = {f2tf32f(w.x), f2tf32f(w.y), f2tf32f(w.z), f2tf32f(w.w)};
            *reinterpret_cast<float4*>(&Bs[i * LDA + j]) = uw;
        }
        __syncthreads();

        #pragma unroll
        for (int ks = 0; ks < 32; ks += 8) {
            FragA af[4];
            FragBc bf[2];
            #pragma unroll
            for (int mt = 0; mt < 4; mt++)
                wmma::load_matrix_sync(af[mt], &As[(wm0 + mt * 16) * LDA + ks], LDA);
            #pragma unroll
            for (int nt = 0; nt < 2; nt++)
                wmma::load_matrix_sync(bf[nt], &Bs[(wn0 + nt * 16) * LDA + ks], LDA);
            #pragma unroll
            for (int mt = 0; mt < 4; mt++)
                #pragma unroll
                for (int nt = 0; nt < 2; nt++)
                    wmma::mma_sync(acc[mt][nt], af[mt], bf[nt], acc[mt][nt]);
        }
        __syncthreads();
    }

    #pragma unroll
    for (int mt = 0; mt < 4; mt++) {
        #pragma unroll
        for (int nt = 0; nt < 2; nt++) {
            wmma::store_matrix_sync(&stage[wid][0], acc[mt][nt], 16, wmma::mem_row_major);
            __syncwarp();
            int r = lane >> 1, c8 = (lane & 1) * 8;
            int gm = bm * 128 + wm0 + mt * 16 + r;
            int gn_t = bn * 128 + wn0 + nt * 16;
            float out[8];
            #pragma unroll
            for (int jj = 0; jj < 8; jj++)
                out[jj] = stage[wid][r * 16 + c8 + jj] + bias[gn_t + c8 + jj];
            float* dst;
            if (OUT_MODE == 0) {
                dst = Y + (size_t)gm * SIZE + gn_t + c8;
            } else {
                int b = gm >> 11, s = gm & 2047;
                int h = gn_t >> 6, d0 = (gn_t & 63) + c8;
                dst = Y + ((((size_t)b * HEADS + h) * SEQ + s) << 6) + d0;
            }
            *reinterpret_cast<float4*>(dst)     = make_float4(out[0], out[1], out[2], out[3]);
            *reinterpret_cast<float4*>(dst + 4) = make_float4(out[4], out[5], out[6], out[7]);
            __syncwarp();
        }
    }
}

// ==================================================================
// Fused causal attention: per (bh, q-tile of 128):
//   Pass A: stats (m, l) via streamed S = (Q/8)K^T tiles (wmma)
//   Pass B: recompute S, write P = exp(S-m)/l to attn, O += P @ V
//   Tiles above diagonal: direct zero writes.
// ==================================================================
__global__ void __launch_bounds__(256) fused_attn(const float* __restrict__ Q,
                                                  const float* __restrict__ Kg,
                                                  const float* __restrict__ Vg,
                                                  float* __restrict__ attn,
                                                  float* __restrict__ Oh) {
    extern __shared__ __align__(16) float smem[];
    float* Qs   = smem;                       // 128*68
    float* Ks   = Qs + 128 * LDQ;             // 128*68
    float* Vs   = Ks + 128 * LDQ;             // 128*68
    float* Ss   = Vs + 128 * LDQ;             // 128*132
    float* mrow = Ss + 128 * LDS_;            // 128
    float* lrow = mrow + 128;                 // 128

    const int tid = threadIdx.x, wid = tid >> 5, lane = tid & 31;
    const int qt = 15 - blockIdx.x;           // big tiles first (wave balance)
    const int bh = blockIdx.y;

    const float* q = Q  + (size_t)bh * SEQ * HDIM;
    const float* k = Kg + (size_t)bh * SEQ * HDIM;
    const float* v = Vg + (size_t)bh * SEQ * HDIM;
    float* arow = attn + ((size_t)bh * SEQ + qt * 128) * SEQ;
    float* orow = Oh + (((size_t)bh * SEQ + qt * 128) << 6);

    // load Q tile (scaled by 1/8, tf32) — 2048 float4s, 8 per thread
    #pragma unroll
    for (int l = 0; l < 8; l++) {
        int f4 = tid + l * 256;
        int i = f4 >> 4, j = (f4 & 15) * 4;
        float4 t = *reinterpret_cast<const float4*>(q + (size_t)(qt * 128 + i) * HDIM + j);
        float4 u = {f2tf32f(t.x * 0.125f), f2tf32f(t.y * 0.125f),
                    f2tf32f(t.z * 0.125f), f2tf32f(t.w * 0.125f)};
        *reinterpret_cast<float4*>(&Qs[i * LDQ + j]) = u;
    }
    if (tid < 128) { mrow[tid] = -INFINITY; lrow[tid] = 0.f; }
    __syncthreads();

    // warp layouts
    const int wm0s = (wid & 1) * 64, wn0s = (wid >> 1) * 32;   // S: 2m x 4n
    const int wm0o = (wid & 3) * 32, wn0o = (wid >> 2) * 32;   // O: 4m x 2n

    // ---------------- Pass A: stats ----------------
    for (int kt = 0; kt <= qt; kt++) {
        #pragma unroll
        for (int l = 0; l < 8; l++) {
            int f4 = tid + l * 256;
            int i = f4 >> 4, j = (f4 & 15) * 4;
            float4 t = *reinterpret_cast<const float4*>(k + (size_t)(kt * 128 + i) * HDIM + j);
            float4 u = {f2tf32f(t.x), f2tf32f(t.y), f2tf32f(t.z), f2tf32f(t.w)};
            *reinterpret_cast<float4*>(&Ks[i * LDQ + j]) = u;
        }
        __syncthreads();

        {
            FragC acc[4][2];
            #pragma unroll
            for (int mt = 0; mt < 4; mt++)
                #pragma unroll
                for (int nt = 0; nt < 2; nt++) wmma::fill_fragment(acc[mt][nt], 0.0f);
            #pragma unroll
            for (int ks = 0; ks < 64; ks += 8) {
                FragA af[4];
                FragBc bf[2];
                #pragma unroll
                for (int mt = 0; mt < 4; mt++)
                    wmma::load_matrix_sync(af[mt], &Qs[(wm0s + mt * 16) * LDQ + ks], LDQ);
                #pragma unroll
                for (int nt = 0; nt < 2; nt++)
                    wmma::load_matrix_sync(bf[nt], &Ks[(wn0s + nt * 16) * LDQ + ks], LDQ);
                #pragma unroll
                for (int mt = 0; mt < 4; mt++)
                    #pragma unroll
                    for (int nt = 0; nt < 2; nt++)
                        wmma::mma_sync(acc[mt][nt], af[mt], bf[nt], acc[mt][nt]);
            }
            #pragma unroll
            for (int mt = 0; mt < 4; mt++)
                #pragma unroll
                for (int nt = 0; nt < 2; nt++)
                    wmma::store_matrix_sync(&Ss[(wm0s + mt * 16) * LDS_ + wn0s + nt * 16],
                                            acc[mt][nt], LDS_, wmma::mem_row_major);
        }
        __syncthreads();

        // stats: warp w owns rows w*16 .. w*16+15; lane covers cols lane*4..+3
        const bool diag = (kt == qt);
        #pragma unroll
        for (int r16 = 0; r16 < 16; r16++) {
            int row = wid * 16 + r16;
            float4 s = *reinterpret_cast<const float4*>(&Ss[row * LDS_ + lane * 4]);
            if (diag) {
                int c = lane * 4;
                if (c + 0 > row) s.x = -INFINITY;
                if (c + 1 > row) s.y = -INFINITY;
                if (c + 2 > row) s.z = -INFINITY;
                if (c + 3 > row) s.w = -INFINITY;
            }
            float lm = fmaxf(fmaxf(s.x, s.y), fmaxf(s.z, s.w));
            #pragma unroll
            for (int o = 16; o; o >>= 1) lm = fmaxf(lm, __shfl_xor_sync(~0u, lm, o));
            float mold = mrow[row];
            float mnew = fmaxf(mold, lm);
            float ps = __expf(s.x - mnew) + __expf(s.y - mnew)
                     + __expf(s.z - mnew) + __expf(s.w - mnew);
            #pragma unroll
            for (int o = 16; o; o >>= 1) ps += __shfl_xor_sync(~0u, ps, o);
            if (lane == 0) {
                lrow[row] = lrow[row] * __expf(mold - mnew) + ps;
                mrow[row] = mnew;
            }
        }
        __syncthreads();
    }

    if (tid < 128) lrow[tid] = 1.0f / lrow[tid];
    __syncthreads();

    // ---------------- Pass B: write P, accumulate O ----------------
    FragC oacc[2][2];
    #pragma unroll
    for (int mt = 0; mt < 2; mt++)
        #pragma unroll
        for (int nt = 0; nt < 2; nt++) wmma::fill_fragment(oacc[mt][nt], 0.0f);

    for (int kt = 0; kt <= qt; kt++) {
        #pragma unroll
        for (int l = 0; l < 8; l++) {
            int f4 = tid + l * 256;
            int i = f4 >> 4, j = (f4 & 15) * 4;
            float4 t = *reinterpret_cast<const float4*>(k + (size_t)(kt * 128 + i) * HDIM + j);
            float4 u = {f2tf32f(t.x), f2tf32f(t.y), f2tf32f(t.z), f2tf32f(t.w)};
            *reinterpret_cast<float4*>(&Ks[i * LDQ + j]) = u;
            float4 tv = *reinterpret_cast<const float4*>(v + (size_t)(kt * 128 + i) * HDIM + j);
            float4 uv = {f2tf32f(tv.x), f2tf32f(tv.y), f2tf32f(tv.z), f2tf32f(tv.w)};
            *reinterpret_cast<float4*>(&Vs[i * LDQ + j]) = uv;
        }
        __syncthreads();

        {
            FragC acc[4][2];
            #pragma unroll
            for (int mt = 0; mt < 4; mt++)
                #pragma unroll
                for (int nt = 0; nt < 2; nt++) wmma::fill_fragment(acc[mt][nt], 0.0f);
            #pragma unroll
            for (int ks = 0; ks < 64; ks += 8) {
                FragA af[4];
                FragBc bf[2];
                #pragma unroll
                for (int mt = 0; mt < 4; mt++)
                    wmma::load_matrix_sync(af[mt], &Qs[(wm0s + mt * 16) * LDQ + ks], LDQ);
                #pragma unroll
                for (int nt = 0; nt < 2; nt++)
                    wmma::load_matrix_sync(bf[nt], &Ks[(wn0s + nt * 16) * LDQ + ks], LDQ);
                #pragma unroll
                for (int mt = 0; mt < 4; mt++)
                    #pragma unroll
                    for (int nt = 0; nt < 2; nt++)
                        wmma::mma_sync(acc[mt][nt], af[mt], bf[nt], acc[mt][nt]);
            }
            #pragma unroll
            for (int mt = 0; mt < 4; mt++)
                #pragma unroll
                for (int nt = 0; nt < 2; nt++)
                    wmma::store_matrix_sync(&Ss[(wm0s + mt * 16) * LDS_ + wn0s + nt * 16],
                                            acc[mt][nt], LDS_, wmma::mem_row_major);
        }
        __syncthreads();

        // P = exp(S - m) * invl; write to attn; store tf32(P) back to Ss
        const bool diag = (kt == qt);
        #pragma unroll
        for (int r16 = 0; r16 < 16; r16++) {
            int row = wid * 16 + r16;
            float m = mrow[row], il = lrow[row];
            float4 s = *reinterpret_cast<const float4*>(&Ss[row * LDS_ + lane * 4]);
            float4 p;
            p.x = __expf(s.x - m) * il;
            p.y = __expf(s.y - m) * il;
            p.z = __expf(s.z - m) * il;
            p.w = __expf(s.w - m) * il;
            if (diag) {
                int c = lane * 4;
                if (c + 0 > row) p.x = 0.f;
                if (c + 1 > row) p.y = 0.f;
                if (c + 2 > row) p.z = 0.f;
                if (c + 3 > row) p.w = 0.f;
            }
            *reinterpret_cast<float4*>(arow + (size_t)row * SEQ + kt * 128 + lane * 4) = p;
            float4 pt = {f2tf32f(p.x), f2tf32f(p.y), f2tf32f(p.z), f2tf32f(p.w)};
            *reinterpret_cast<float4*>(&Ss[row * LDS_ + lane * 4]) = pt;
        }
        __syncthreads();

        // O += P @ V  (P row-major from Ss, V row-major from Vs)
        #pragma unroll
        for (int ks = 0; ks < 128; ks += 8) {
            FragA af[2];
            FragBr bf[2];
            #pragma unroll
            for (int mt = 0; mt < 2; mt++)
                wmma::load_matrix_sync(af[mt], &Ss[(wm0o + mt * 16) * LDS_ + ks], LDS_);
            #pragma unroll
            for (int nt = 0; nt < 2; nt++)
                wmma::load_matrix_sync(bf[nt], &Vs[ks * LDQ + wn0o + nt * 16], LDQ);
            #pragma unroll
            for (int mt = 0; mt < 2; mt++)
                #pragma unroll
                for (int nt = 0; nt < 2; nt++)
                    wmma::mma_sync(oacc[mt][nt], af[mt], bf[nt], oacc[mt][nt]);
        }
        __syncthreads();
    }

    // zero tiles above the diagonal
    const float4 z4 = {0.f, 0.f, 0.f, 0.f};
    for (int kt = qt + 1; kt < 16; kt++) {
        #pragma unroll
        for (int r16 = 0; r16 < 16; r16++) {
            int row = wid * 16 + r16;
            *reinterpret_cast<float4*>(arow + (size_t)row * SEQ + kt * 128 + lane * 4) = z4;
        }
    }

    // store O: stage fragments into Ss, then coalesced copy out
    #pragma unroll
    for (int mt = 0; mt < 2; mt++)
        #pragma unroll
        for (int nt = 0; nt < 2; nt++)
            wmma::store_matrix_sync(&Ss[(wm0o + mt * 16) * LDS_ + wn0o + nt * 16],
                                    oacc[mt][nt], LDS_, wmma::mem_row_major);
    __syncthreads();
    #pragma unroll
    for (int l = 0; l < 8; l++) {
        int f4 = tid + l * 256;              // 0..2047
        int i = f4 >> 4, j = (f4 & 15) * 4;  // row, col(0..60)
        float4 t = *reinterpret_cast<const float4*>(&Ss[i * LDS_ + j]);
        *reinterpret_cast<float4*>(orow + ((size_t)i << 6) + j) = t;
    }
}

// ==================================================================
// host launcher
// ==================================================================
extern "C" void kernel_launch(void* const* d_in, const int* in_sizes, int n_in,
                              void* d_out, int out_size) {
    const float* key   = (const float*)d_in[0];
    const float* value = (const float*)d_in[1];
    const float* query = (const float*)d_in[2];
    const float* Wk = (const float*)d_in[4];
    const float* bk = (const float*)d_in[5];
    const float* Wv = (const float*)d_in[6];
    const float* bv = (const float*)d_in[7];
    const float* Wq = (const float*)d_in[8];
    const float* bq = (const float*)d_in[9];
    const float* Wo = (const float*)d_in[10];
    const float* bo = (const float*)d_in[11];

    float *qh, *kh, *vh, *oh, *attn_scr, *out_scr;
    cudaGetSymbolAddress((void**)&qh, g_q);
    cudaGetSymbolAddress((void**)&kh, g_k);
    cudaGetSymbolAddress((void**)&vh, g_v);
    cudaGetSymbolAddress((void**)&oh, g_oh);
    cudaGetSymbolAddress((void**)&attn_scr, g_attn_scratch);
    cudaGetSymbolAddress((void**)&out_scr, g_out_scratch);

    const long long OUT_ELE  = (long long)M_TOK * SIZE;
    const long long ATTN_ELE = (long long)BH * SEQ * SEQ;

    float* dout = (float*)d_out;
    float* outp;
    float* attnp;
    if ((long long)out_size >= OUT_ELE + ATTN_ELE) {
        outp = dout; attnp = dout + OUT_ELE;
    } else if ((long long)out_size == ATTN_ELE) {
        attnp = dout; outp = out_scr;
    } else {
        outp = dout; attnp = attn_scr;
    }

    // fused kernel smem: Q + K + V (128*68 each) + S (128*132) + m + l
    const int SMEM_FUSED = (3 * 128 * LDQ + 128 * LDS_ + 256) * 4;
    cudaFuncSetAttribute(fused_attn, cudaFuncAttributeMaxDynamicSharedMemorySize, SMEM_FUSED);

    dim3 thr(256);
    dim3 gProj(SIZE / 128, M_TOK / 128);           // (8, 32)

    proj_wmma<0, 1><<<gProj, thr>>>(query, Wq, bq, qh);
    proj_wmma<0, 1><<<gProj, thr>>>(key,   Wk, bk, kh);
    proj_wmma<0, 1><<<gProj, thr>>>(value, Wv, bv, vh);

    dim3 gFused(SEQ / 128, BH);                    // (16, 32)
    fused_attn<<<gFused, thr, SMEM_FUSED>>>(qh, kh, vh, attnp, oh);

    proj_wmma<1, 0><<<gProj, thr>>>(oh, Wo, bo, outp);
}

// round 8
// speedup vs baseline: 1.7608x; 1.7608x over previous
#include <cuda_runtime.h>
#include <mma.h>
#include <cstdint>
#include <math.h>

using namespace nvcuda;

// Problem constants
#define BATCH 2
#define SEQ   2048
#define SIZE  1024
#define HEADS 16
#define HDIM  64
#define M_TOK (BATCH * SEQ)
#define BH    (BATCH * HEADS)
#define NQT   (SEQ / 128)     // 16 q-tiles

// -------- scratch (device globals; no allocations allowed) --------
__device__ float g_q[(size_t)BH * SEQ * HDIM];        // [bh, s, d]
__device__ float g_k[(size_t)BH * SEQ * HDIM];        // [bh, s, d]
__device__ float g_v[(size_t)BH * SEQ * HDIM];        // [bh, s, d]
__device__ float g_oh[(size_t)BH * SEQ * HDIM];       // [bh, s, d]
__device__ float g_psum[(size_t)BH * SEQ * NQT];      // per-row, per-k-tile exp sums
__device__ float g_attn_scratch[(size_t)BH * SEQ * SEQ];
__device__ float g_out_scratch[(size_t)M_TOK * SIZE];

__device__ __forceinline__ float f2tf32f(float x) {
    uint32_t r;
    asm("cvt.rna.tf32.f32 %0, %1;" : "=r"(r) : "f"(x));
    return __uint_as_float(r);
}

typedef wmma::fragment<wmma::matrix_a, 16, 16, 8, wmma::precision::tf32, wmma::row_major> FragA;
typedef wmma::fragment<wmma::matrix_b, 16, 16, 8, wmma::precision::tf32, wmma::col_major> FragBc;
typedef wmma::fragment<wmma::matrix_b, 16, 16, 8, wmma::precision::tf32, wmma::row_major> FragBr;
typedef wmma::fragment<wmma::accumulator, 16, 16, 8, float> FragC;

#define LDA 36   // smem leading dim for 32-wide K tiles (pad 4)
#define LDV 68   // smem leading dim for 64-wide V tiles (pad 4)

// ==================================================================
// Projection GEMM: Y = X @ W^T + bias.  M=4096, N=1024, K=1024.
// ==================================================================
template<int IN_MODE, int OUT_MODE>
__global__ void __launch_bounds__(256) proj_wmma(const float* __restrict__ X,
                                                 const float* __restrict__ W,
                                                 const float* __restrict__ bias,
                                                 float* __restrict__ Y) {
    __shared__ __align__(16) float As[128 * LDA];
    __shared__ __align__(16) float Bs[128 * LDA];
    __shared__ __align__(16) float stage[8][272];

    const int tid = threadIdx.x, wid = tid >> 5, lane = tid & 31;
    const int bm = blockIdx.y, bn = blockIdx.x;
    const int wm0 = (wid & 1) * 64, wn0 = (wid >> 1) * 32;

    FragC acc[4][2];
    #pragma unroll
    for (int mt = 0; mt < 4; mt++)
        #pragma unroll
        for (int nt = 0; nt < 2; nt++) wmma::fill_fragment(acc[mt][nt], 0.0f);

    for (int kc = 0; kc < 1024; kc += 32) {
        #pragma unroll
        for (int l = 0; l < 4; l++) {
            int v = tid + l * 256;
            int i = v >> 3;
            int j = (v & 7) * 4;
            float4 t;
            if (IN_MODE == 0) {
                t = *reinterpret_cast<const float4*>(
                    X + (size_t)(bm * 128 + i) * 1024 + kc + j);
            } else {
                int gm = bm * 128 + i;
                int b = gm >> 11, s = gm & 2047;
                int h = kc >> 6, d0 = kc & 63;
                t = *reinterpret_cast<const float4*>(
                    X + ((((size_t)b * HEADS + h) * SEQ + s) << 6) + d0 + j);
            }
            float4 u = {f2tf32f(t.x), f2tf32f(t.y), f2tf32f(t.z), f2tf32f(t.w)};
            *reinterpret_cast<float4*>(&As[i * LDA + j]) = u;
            float4 w = *reinterpret_cast<const float4*>(
                W + (size_t)(bn * 128 + i) * 1024 + kc + j);
            float4 uw = {f2tf32f(w.x), f2tf32f(w.y), f2tf32f(w.z), f2tf32f(w.w)};
            *reinterpret_cast<float4*>(&Bs[i * LDA + j]) = uw;
        }
        __syncthreads();

        #pragma unroll
        for (int ks = 0; ks < 32; ks += 8) {
            FragA af[4];
            FragBc bf[2];
            #pragma unroll
            for (int mt = 0; mt < 4; mt++)
                wmma::load_matrix_sync(af[mt], &As[(wm0 + mt * 16) * LDA + ks], LDA);
            #pragma unroll
            for (int nt = 0; nt < 2; nt++)
                wmma::load_matrix_sync(bf[nt], &Bs[(wn0 + nt * 16) * LDA + ks], LDA);
            #pragma unroll
            for (int mt = 0; mt < 4; mt++)
                #pragma unroll
                for (int nt = 0; nt < 2; nt++)
                    wmma::mma_sync(acc[mt][nt], af[mt], bf[nt], acc[mt][nt]);
        }
        __syncthreads();
    }

    #pragma unroll
    for (int mt = 0; mt < 4; mt++) {
        #pragma unroll
        for (int nt = 0; nt < 2; nt++) {
            wmma::store_matrix_sync(&stage[wid][0], acc[mt][nt], 16, wmma::mem_row_major);
            __syncwarp();
            int r = lane >> 1, c8 = (lane & 1) * 8;
            int gm = bm * 128 + wm0 + mt * 16 + r;
            int gn_t = bn * 128 + wn0 + nt * 16;
            float out[8];
            #pragma unroll
            for (int jj = 0; jj < 8; jj++)
                out[jj] = stage[wid][r * 16 + c8 + jj] + bias[gn_t + c8 + jj];
            float* dst;
            if (OUT_MODE == 0) {
                dst = Y + (size_t)gm * SIZE + gn_t + c8;
            } else {
                int b = gm >> 11, s = gm & 2047;
                int h = gn_t >> 6, d0 = (gn_t & 63) + c8;
                dst = Y + ((((size_t)b * HEADS + h) * SEQ + s) << 6) + d0;
            }
            *reinterpret_cast<float4*>(dst)     = make_float4(out[0], out[1], out[2], out[3]);
            *reinterpret_cast<float4*>(dst + 4) = make_float4(out[4], out[5], out[6], out[7]);
            __syncwarp();
        }
    }
}

// ==================================================================
// scores_exp: E[bh,q,k] = exp((Q.K^T)/8) with causal mask (0 above diag),
// lower-triangular 128x128 tiles only. Also writes per-row partial sums
// to g_psum[(bh*16+bm)*128+row][bn]  (deterministic reduction).
// ==================================================================
__global__ void __launch_bounds__(256) scores_exp(const float* __restrict__ Q,
                                                  const float* __restrict__ Kh,
                                                  float* __restrict__ attn,
                                                  float* __restrict__ psum) {
    const int bn = blockIdx.x, bm = blockIdx.y, bh = blockIdx.z;
    if (bn > bm) return;
    __shared__ __align__(16) float As[128 * LDA];
    __shared__ __align__(16) float Bs[128 * LDA];
    __shared__ __align__(16) float stage[8][272];
    __shared__ float psums_sm[128][4];

    const int tid = threadIdx.x, wid = tid >> 5, lane = tid & 31;
    const int wm0 = (wid & 1) * 64, wng = wid >> 1;
    const int wn0 = wng * 32;
    const float* q = Q + (size_t)bh * SEQ * HDIM;
    const float* k = Kh + (size_t)bh * SEQ * HDIM;
    const bool diag = (bm == bn);

    FragC acc[4][2];
    #pragma unroll
    for (int mt = 0; mt < 4; mt++)
        #pragma unroll
        for (int nt = 0; nt < 2; nt++) wmma::fill_fragment(acc[mt][nt], 0.0f);

    for (int kc = 0; kc < HDIM; kc += 32) {
        #pragma unroll
        for (int l = 0; l < 4; l++) {
            int v = tid + l * 256;
            int i = v >> 3;
            int j = (v & 7) * 4;
            float4 t = *reinterpret_cast<const float4*>(
                q + (size_t)(bm * 128 + i) * HDIM + kc + j);
            float4 u = {f2tf32f(t.x), f2tf32f(t.y), f2tf32f(t.z), f2tf32f(t.w)};
            *reinterpret_cast<float4*>(&As[i * LDA + j]) = u;
            float4 w = *reinterpret_cast<const float4*>(
                k + (size_t)(bn * 128 + i) * HDIM + kc + j);
            float4 uw = {f2tf32f(w.x), f2tf32f(w.y), f2tf32f(w.z), f2tf32f(w.w)};
            *reinterpret_cast<float4*>(&Bs[i * LDA + j]) = uw;
        }
        __syncthreads();

        #pragma unroll
        for (int ks = 0; ks < 32; ks += 8) {
            FragA af[4];
            FragBc bf[2];
            #pragma unroll
            for (int mt = 0; mt < 4; mt++)
                wmma::load_matrix_sync(af[mt], &As[(wm0 + mt * 16) * LDA + ks], LDA);
            #pragma unroll
            for (int nt = 0; nt < 2; nt++)
                wmma::load_matrix_sync(bf[nt], &Bs[(wn0 + nt * 16) * LDA + ks], LDA);
            #pragma unroll
            for (int mt = 0; mt < 4; mt++)
                #pragma unroll
                for (int nt = 0; nt < 2; nt++)
                    wmma::mma_sync(acc[mt][nt], af[mt], bf[nt], acc[mt][nt]);
        }
        __syncthreads();
    }

    // epilogue: E = exp(S*0.125) with causal mask; row partial sums
    #pragma unroll
    for (int mt = 0; mt < 4; mt++) {
        float rowsum = 0.f;   // per-lane; row = wm0+mt*16+(lane>>1)
        #pragma unroll
        for (int nt = 0; nt < 2; nt++) {
            wmma::store_matrix_sync(&stage[wid][0], acc[mt][nt], 16, wmma::mem_row_major);
            __syncwarp();
            int r = lane >> 1, c8 = (lane & 1) * 8;
            int gq = bm * 128 + wm0 + mt * 16 + r;
            int gk0 = bn * 128 + wn0 + nt * 16 + c8;
            float e[8];
            #pragma unroll
            for (int jj = 0; jj < 8; jj++) {
                float s = stage[wid][r * 16 + c8 + jj] * 0.125f;
                float v = __expf(s);
                if (diag && (gk0 + jj > gq)) v = 0.f;
                e[jj] = v;
                rowsum += v;
            }
            float* dst = attn + ((size_t)bh * SEQ + gq) * SEQ + gk0;
            *reinterpret_cast<float4*>(dst)     = make_float4(e[0], e[1], e[2], e[3]);
            *reinterpret_cast<float4*>(dst + 4) = make_float4(e[4], e[5], e[6], e[7]);
            __syncwarp();
        }
        rowsum += __shfl_xor_sync(~0u, rowsum, 1);
        if ((lane & 1) == 0)
            psums_sm[wm0 + mt * 16 + (lane >> 1)][wng] = rowsum;
    }
    __syncthreads();
    if (tid < 128) {
        float s = psums_sm[tid][0] + psums_sm[tid][1]
                + psums_sm[tid][2] + psums_sm[tid][3];
        psum[((size_t)(bh * NQT + bm) * 128 + tid) * NQT + bn] = s;
    }
}

// ==================================================================
// attnv_norm: per (qt, bh) CTA 128q x 64d.
//  - builds il = 1/sum from g_psum
//  - streams E chunks, writes P = E*il in-place, MMA P@V
//  - zero-fills columns above the causal boundary
// ==================================================================
__global__ void __launch_bounds__(256) attnv_norm(float* __restrict__ attn,
                                                  const float* __restrict__ V,
                                                  const float* __restrict__ psum,
                                                  float* __restrict__ Oh) {
    const int qt = (NQT - 1) - blockIdx.x;   // big tiles first
    const int bh = blockIdx.y;
    __shared__ __align__(16) float As[128 * LDA];
    __shared__ __align__(16) float Vs[32 * LDV];
    __shared__ __align__(16) float stage[8][272];
    __shared__ float ilrow[128];

    const int tid = threadIdx.x, wid = tid >> 5, lane = tid & 31;
    const int wm0 = (wid & 3) * 32, wn0 = (wid >> 2) * 32;
    float* a = attn + ((size_t)bh * SEQ + qt * 128) * SEQ;
    const float* v = V + (size_t)bh * SEQ * HDIM;

    if (tid < 128) {
        const float* ps = psum + ((size_t)(bh * NQT + qt) * 128 + tid) * NQT;
        float s = 0.f;
        for (int t = 0; t <= qt; t++) s += ps[t];
        ilrow[tid] = 1.0f / s;
    }
    __syncthreads();

    FragC acc[2][2];
    #pragma unroll
    for (int mt = 0; mt < 2; mt++)
        #pragma unroll
        for (int nt = 0; nt < 2; nt++) wmma::fill_fragment(acc[mt][nt], 0.0f);

    const int kend = (qt + 1) * 128;
    for (int kc = 0; kc < kend; kc += 32) {
        #pragma unroll
        for (int l = 0; l < 4; l++) {
            int vv = tid + l * 256;
            int i = vv >> 3;
            int j = (vv & 7) * 4;
            float il = ilrow[i];
            float* src = a + (size_t)i * SEQ + kc + j;
            float4 t = *reinterpret_cast<const float4*>(src);
            t.x *= il; t.y *= il; t.z *= il; t.w *= il;
            *reinterpret_cast<float4*>(src) = t;      // P back to gmem
            float4 u = {f2tf32f(t.x), f2tf32f(t.y), f2tf32f(t.z), f2tf32f(t.w)};
            *reinterpret_cast<float4*>(&As[i * LDA + j]) = u;
        }
        #pragma unroll
        for (int l = 0; l < 2; l++) {
            int vv = tid + l * 256;
            int i = vv >> 4;
            int j = (vv & 15) * 4;
            float4 t = *reinterpret_cast<const float4*>(
                v + (size_t)(kc + i) * HDIM + j);
            float4 u = {f2tf32f(t.x), f2tf32f(t.y), f2tf32f(t.z), f2tf32f(t.w)};
            *reinterpret_cast<float4*>(&Vs[i * LDV + j]) = u;
        }
        __syncthreads();

        #pragma unroll
        for (int ks = 0; ks < 32; ks += 8) {
            FragA af[2];
            FragBr bf[2];
            #pragma unroll
            for (int mt = 0; mt < 2; mt++)
                wmma::load_matrix_sync(af[mt], &As[(wm0 + mt * 16) * LDA + ks], LDA);
            #pragma unroll
            for (int nt = 0; nt < 2; nt++)
                wmma::load_matrix_sync(bf[nt], &Vs[ks * LDV + wn0 + nt * 16], LDV);
            #pragma unroll
            for (int mt = 0; mt < 2; mt++)
                #pragma unroll
                for (int nt = 0; nt < 2; nt++)
                    wmma::mma_sync(acc[mt][nt], af[mt], bf[nt], acc[mt][nt]);
        }
        __syncthreads();
    }

    // zero-fill columns kend..SEQ for this CTA's 128 rows
    {
        const float4 z4 = {0.f, 0.f, 0.f, 0.f};
        int ncols4 = (SEQ - kend) >> 2;           // float4s per row
        int total4 = 128 * ncols4;
        for (int idx = tid; idx < total4; idx += 256) {
            int i = idx / ncols4, j4 = idx - i * ncols4;
            *reinterpret_cast<float4*>(a + (size_t)i * SEQ + kend + j4 * 4) = z4;
        }
    }

    #pragma unroll
    for (int mt = 0; mt < 2; mt++) {
        #pragma unroll
        for (int nt = 0; nt < 2; nt++) {
            wmma::store_matrix_sync(&stage[wid][0], acc[mt][nt], 16, wmma::mem_row_major);
            __syncwarp();
            int r = lane >> 1, c8 = (lane & 1) * 8;
            int gq = qt * 128 + wm0 + mt * 16 + r;
            int d0 = wn0 + nt * 16 + c8;
            float out[8];
            #pragma unroll
            for (int jj = 0; jj < 8; jj++)
                out[jj] = stage[wid][r * 16 + c8 + jj];
            float* dst = Oh + (((size_t)bh * SEQ + gq) << 6) + d0;
            *reinterpret_cast<float4*>(dst)     = make_float4(out[0], out[1], out[2], out[3]);
            *reinterpret_cast<float4*>(dst + 4) = make_float4(out[4], out[5], out[6], out[7]);
            __syncwarp();
        }
    }
}

// ==================================================================
// host launcher
// ==================================================================
extern "C" void kernel_launch(void* const* d_in, const int* in_sizes, int n_in,
                              void* d_out, int out_size) {
    const float* key   = (const float*)d_in[0];
    const float* value = (const float*)d_in[1];
    const float* query = (const float*)d_in[2];
    const float* Wk = (const float*)d_in[4];
    const float* bk = (const float*)d_in[5];
    const float* Wv = (const float*)d_in[6];
    const float* bv = (const float*)d_in[7];
    const float* Wq = (const float*)d_in[8];
    const float* bq = (const float*)d_in[9];
    const float* Wo = (const float*)d_in[10];
    const float* bo = (const float*)d_in[11];

    float *qh, *kh, *vh, *oh, *psum, *attn_scr, *out_scr;
    cudaGetSymbolAddress((void**)&qh, g_q);
    cudaGetSymbolAddress((void**)&kh, g_k);
    cudaGetSymbolAddress((void**)&vh, g_v);
    cudaGetSymbolAddress((void**)&oh, g_oh);
    cudaGetSymbolAddress((void**)&psum, g_psum);
    cudaGetSymbolAddress((void**)&attn_scr, g_attn_scratch);
    cudaGetSymbolAddress((void**)&out_scr, g_out_scratch);

    const long long OUT_ELE  = (long long)M_TOK * SIZE;
    const long long ATTN_ELE = (long long)BH * SEQ * SEQ;

    float* dout = (float*)d_out;
    float* outp;
    float* attnp;
    if ((long long)out_size >= OUT_ELE + ATTN_ELE) {
        outp = dout; attnp = dout + OUT_ELE;
    } else if ((long long)out_size == ATTN_ELE) {
        attnp = dout; outp = out_scr;
    } else {
        outp = dout; attnp = attn_scr;
    }

    dim3 thr(256);
    dim3 gProj(SIZE / 128, M_TOK / 128);           // (8, 32)

    proj_wmma<0, 1><<<gProj, thr>>>(query, Wq, bq, qh);
    proj_wmma<0, 1><<<gProj, thr>>>(key,   Wk, bk, kh);
    proj_wmma<0, 1><<<gProj, thr>>>(value, Wv, bv, vh);

    dim3 gScores(NQT, NQT, BH);                    // (16, 16, 32)
    scores_exp<<<gScores, thr>>>(qh, kh, attnp, psum);

    dim3 gAV(NQT, BH);                             // (16, 32)
    attnv_norm<<<gAV, thr>>>(attnp, vh, psum, oh);

    proj_wmma<1, 0><<<gProj, thr>>>(oh, Wo, bo, outp);
}

// round 10
// speedup vs baseline: 1.9928x; 1.1317x over previous
#include <cuda_runtime.h>
#include <mma.h>
#include <cstdint>
#include <math.h>

using namespace nvcuda;

// Problem constants
#define BATCH 2
#define SEQ   2048
#define SIZE  1024
#define HEADS 16
#define HDIM  64
#define M_TOK (BATCH * SEQ)
#define BH    (BATCH * HEADS)
#define NQT   (SEQ / 128)     // 16 q-tiles

// -------- scratch (device globals; no allocations allowed) --------
__device__ float g_q[(size_t)BH * SEQ * HDIM];        // [bh, s, d]
__device__ float g_k[(size_t)BH * SEQ * HDIM];        // [bh, s, d]
__device__ float g_v[(size_t)BH * SEQ * HDIM];        // [bh, s, d]
__device__ float g_oh[(size_t)BH * SEQ * HDIM];       // [bh, s, d]
__device__ float g_psum[(size_t)BH * SEQ * NQT];      // per-row, per-k-tile exp sums
__device__ float g_attn_scratch[(size_t)BH * SEQ * SEQ];
__device__ float g_out_scratch[(size_t)M_TOK * SIZE];

__device__ __forceinline__ float f2tf32f(float x) {
    uint32_t r;
    asm("cvt.rna.tf32.f32 %0, %1;" : "=r"(r) : "f"(x));
    return __uint_as_float(r);
}

typedef wmma::fragment<wmma::matrix_a, 16, 16, 8, wmma::precision::tf32, wmma::row_major> FragA;
typedef wmma::fragment<wmma::matrix_b, 16, 16, 8, wmma::precision::tf32, wmma::col_major> FragBc;
typedef wmma::fragment<wmma::matrix_b, 16, 16, 8, wmma::precision::tf32, wmma::row_major> FragBr;
typedef wmma::fragment<wmma::accumulator, 16, 16, 8, float> FragC;

#define LDA 36   // smem leading dim for 32-wide K tiles (pad 4)
#define LDQ 68   // smem leading dim for 64-wide tiles (pad 4)
#define LDV 68

// dynamic smem sizes (bytes)
#define SMEM_PROJ   ((2*128*LDA*2 + 8*272) * 4)              // 82432
#define SMEM_SCORES ((2*128*LDQ + 8*272 + 128*4) * 4)        // 80384
#define SMEM_ATTNV  ((2*128*LDA + 2*32*LDV + 8*272 + 128)*4) // 63488

// ==================================================================
// proj3: three projections in one launch (z selects q/k/v).
// Y = X @ W^T + bias, output to head layout [bh,s,d].
// 128x128 tile, BK=32, register-prefetch double buffering.
// ==================================================================
__global__ void __launch_bounds__(256, 2) proj3_wmma(
    const float* __restrict__ X0, const float* __restrict__ X1, const float* __restrict__ X2,
    const float* __restrict__ W0, const float* __restrict__ W1, const float* __restrict__ W2,
    const float* __restrict__ b0, const float* __restrict__ b1, const float* __restrict__ b2,
    float* __restrict__ Y0, float* __restrict__ Y1, float* __restrict__ Y2) {
    extern __shared__ __align__(16) float smem[];
    float* As = smem;                       // 2 * 128*LDA
    float* Bs = As + 2 * 128 * LDA;
    float* stage = Bs + 2 * 128 * LDA;      // 8 * 272

    const int z = blockIdx.z;
    const float* X = (z == 0) ? X0 : (z == 1) ? X1 : X2;
    const float* W = (z == 0) ? W0 : (z == 1) ? W1 : W2;
    const float* bias = (z == 0) ? b0 : (z == 1) ? b1 : b2;
    float* Y = (z == 0) ? Y0 : (z == 1) ? Y1 : Y2;

    const int tid = threadIdx.x, wid = tid >> 5, lane = tid & 31;
    const int bm = blockIdx.y, bn = blockIdx.x;
    const int wm0 = (wid & 1) * 64, wn0 = (wid >> 1) * 32;

    FragC acc[4][2];
    #pragma unroll
    for (int mt = 0; mt < 4; mt++)
        #pragma unroll
        for (int nt = 0; nt < 2; nt++) wmma::fill_fragment(acc[mt][nt], 0.0f);

    float4 ra[4], rb[4];
    // initial load (kc = 0)
    #pragma unroll
    for (int l = 0; l < 4; l++) {
        int v = tid + l * 256;
        int i = v >> 3, j = (v & 7) * 4;
        ra[l] = *reinterpret_cast<const float4*>(X + (size_t)(bm * 128 + i) * 1024 + j);
        rb[l] = *reinterpret_cast<const float4*>(W + (size_t)(bn * 128 + i) * 1024 + j);
    }
    #pragma unroll
    for (int l = 0; l < 4; l++) {
        int v = tid + l * 256;
        int i = v >> 3, j = (v & 7) * 4;
        float4 t = ra[l], w = rb[l];
        *reinterpret_cast<float4*>(&As[i * LDA + j]) =
            make_float4(f2tf32f(t.x), f2tf32f(t.y), f2tf32f(t.z), f2tf32f(t.w));
        *reinterpret_cast<float4*>(&Bs[i * LDA + j]) =
            make_float4(f2tf32f(w.x), f2tf32f(w.y), f2tf32f(w.z), f2tf32f(w.w));
    }
    __syncthreads();

    for (int c = 0; c < 32; c++) {
        const int buf = c & 1;
        const bool nxt = (c + 1 < 32);
        if (nxt) {
            const int kc = (c + 1) * 32;
            #pragma unroll
            for (int l = 0; l < 4; l++) {
                int v = tid + l * 256;
                int i = v >> 3, j = (v & 7) * 4;
                ra[l] = *reinterpret_cast<const float4*>(X + (size_t)(bm * 128 + i) * 1024 + kc + j);
                rb[l] = *reinterpret_cast<const float4*>(W + (size_t)(bn * 128 + i) * 1024 + kc + j);
            }
        }
        const float* Ab = As + buf * 128 * LDA;
        const float* Bb = Bs + buf * 128 * LDA;
        #pragma unroll
        for (int ks = 0; ks < 32; ks += 8) {
            FragA af[4];
            FragBc bf[2];
            #pragma unroll
            for (int mt = 0; mt < 4; mt++)
                wmma::load_matrix_sync(af[mt], &Ab[(wm0 + mt * 16) * LDA + ks], LDA);
            #pragma unroll
            for (int nt = 0; nt < 2; nt++)
                wmma::load_matrix_sync(bf[nt], &Bb[(wn0 + nt * 16) * LDA + ks], LDA);
            #pragma unroll
            for (int mt = 0; mt < 4; mt++)
                #pragma unroll
                for (int nt = 0; nt < 2; nt++)
                    wmma::mma_sync(acc[mt][nt], af[mt], bf[nt], acc[mt][nt]);
        }
        if (nxt) {
            float* An = As + (buf ^ 1) * 128 * LDA;
            float* Bn = Bs + (buf ^ 1) * 128 * LDA;
            #pragma unroll
            for (int l = 0; l < 4; l++) {
                int v = tid + l * 256;
                int i = v >> 3, j = (v & 7) * 4;
                float4 t = ra[l], w = rb[l];
                *reinterpret_cast<float4*>(&An[i * LDA + j]) =
                    make_float4(f2tf32f(t.x), f2tf32f(t.y), f2tf32f(t.z), f2tf32f(t.w));
                *reinterpret_cast<float4*>(&Bn[i * LDA + j]) =
                    make_float4(f2tf32f(w.x), f2tf32f(w.y), f2tf32f(w.z), f2tf32f(w.w));
            }
        }
        __syncthreads();
    }

    // epilogue: head-layout store with bias
    float* st = stage + wid * 272;
    #pragma unroll
    for (int mt = 0; mt < 4; mt++) {
        #pragma unroll
        for (int nt = 0; nt < 2; nt++) {
            wmma::store_matrix_sync(st, acc[mt][nt], 16, wmma::mem_row_major);
            __syncwarp();
            int r = lane >> 1, c8 = (lane & 1) * 8;
            int gm = bm * 128 + wm0 + mt * 16 + r;
            int gn_t = bn * 128 + wn0 + nt * 16;
            float out[8];
            #pragma unroll
            for (int jj = 0; jj < 8; jj++)
                out[jj] = st[r * 16 + c8 + jj] + bias[gn_t + c8 + jj];
            int b = gm >> 11, s = gm & 2047;
            int h = gn_t >> 6, d0 = (gn_t & 63) + c8;
            float* dst = Y + ((((size_t)b * HEADS + h) * SEQ + s) << 6) + d0;
            *reinterpret_cast<float4*>(dst)     = make_float4(out[0], out[1], out[2], out[3]);
            *reinterpret_cast<float4*>(dst + 4) = make_float4(out[4], out[5], out[6], out[7]);
            __syncwarp();
        }
    }
}

// ==================================================================
// scores_exp: E = exp((Q.K^T)/8) with causal mask; single smem load
// (K=64 entirely resident). Upper-tri CTAs write zeros. Row partial
// sums -> g_psum.
// ==================================================================
__global__ void __launch_bounds__(256, 2) scores_exp(const float* __restrict__ Q,
                                                     const float* __restrict__ Kh,
                                                     float* __restrict__ attn,
                                                     float* __restrict__ psum) {
    const int bn = blockIdx.x, bm = blockIdx.y, bh = blockIdx.z;
    const int tid = threadIdx.x;

    if (bn > bm) {
        // zero-fill this 128x128 tile of attn
        const float4 z4 = {0.f, 0.f, 0.f, 0.f};
        float* base = attn + ((size_t)bh * SEQ + bm * 128) * SEQ + bn * 128;
        #pragma unroll
        for (int l = 0; l < 16; l++) {
            int idx = tid + l * 256;        // 0..4095
            int i = idx >> 5, j4 = idx & 31;
            *reinterpret_cast<float4*>(base + (size_t)i * SEQ + j4 * 4) = z4;
        }
        return;
    }

    extern __shared__ __align__(16) float smem[];
    float* Qs = smem;                      // 128*LDQ
    float* Ks = Qs + 128 * LDQ;            // 128*LDQ
    float* stage = Ks + 128 * LDQ;         // 8*272
    float* psums_sm = stage + 8 * 272;     // 128*4

    const int wid = tid >> 5, lane = tid & 31;
    const int wm0 = (wid & 1) * 64, wng = wid >> 1;
    const int wn0 = wng * 32;
    const float* q = Q + (size_t)bh * SEQ * HDIM;
    const float* k = Kh + (size_t)bh * SEQ * HDIM;
    const bool diag = (bm == bn);

    // load full Q,K tiles (128x64 each)
    #pragma unroll
    for (int l = 0; l < 8; l++) {
        int f4 = tid + l * 256;
        int i = f4 >> 4, j = (f4 & 15) * 4;
        float4 t = *reinterpret_cast<const float4*>(q + (size_t)(bm * 128 + i) * HDIM + j);
        *reinterpret_cast<float4*>(&Qs[i * LDQ + j]) =
            make_float4(f2tf32f(t.x), f2tf32f(t.y), f2tf32f(t.z), f2tf32f(t.w));
        float4 w = *reinterpret_cast<const float4*>(k + (size_t)(bn * 128 + i) * HDIM + j);
        *reinterpret_cast<float4*>(&Ks[i * LDQ + j]) =
            make_float4(f2tf32f(w.x), f2tf32f(w.y), f2tf32f(w.z), f2tf32f(w.w));
    }
    __syncthreads();

    FragC acc[4][2];
    #pragma unroll
    for (int mt = 0; mt < 4; mt++)
        #pragma unroll
        for (int nt = 0; nt < 2; nt++) wmma::fill_fragment(acc[mt][nt], 0.0f);

    #pragma unroll
    for (int ks = 0; ks < 64; ks += 8) {
        FragA af[4];
        FragBc bf[2];
        #pragma unroll
        for (int mt = 0; mt < 4; mt++)
            wmma::load_matrix_sync(af[mt], &Qs[(wm0 + mt * 16) * LDQ + ks], LDQ);
        #pragma unroll
        for (int nt = 0; nt < 2; nt++)
            wmma::load_matrix_sync(bf[nt], &Ks[(wn0 + nt * 16) * LDQ + ks], LDQ);
        #pragma unroll
        for (int mt = 0; mt < 4; mt++)
            #pragma unroll
            for (int nt = 0; nt < 2; nt++)
                wmma::mma_sync(acc[mt][nt], af[mt], bf[nt], acc[mt][nt]);
    }

    // epilogue: E = exp(S*0.125) masked; partial row sums
    float* st = stage + wid * 272;
    #pragma unroll
    for (int mt = 0; mt < 4; mt++) {
        float rowsum = 0.f;
        #pragma unroll
        for (int nt = 0; nt < 2; nt++) {
            wmma::store_matrix_sync(st, acc[mt][nt], 16, wmma::mem_row_major);
            __syncwarp();
            int r = lane >> 1, c8 = (lane & 1) * 8;
            int gq = bm * 128 + wm0 + mt * 16 + r;
            int gk0 = bn * 128 + wn0 + nt * 16 + c8;
            float e[8];
            #pragma unroll
            for (int jj = 0; jj < 8; jj++) {
                float s = st[r * 16 + c8 + jj] * 0.125f;
                float v = __expf(s);
                if (diag && (gk0 + jj > gq)) v = 0.f;
                e[jj] = v;
                rowsum += v;
            }
            float* dst = attn + ((size_t)bh * SEQ + gq) * SEQ + gk0;
            *reinterpret_cast<float4*>(dst)     = make_float4(e[0], e[1], e[2], e[3]);
            *reinterpret_cast<float4*>(dst + 4) = make_float4(e[4], e[5], e[6], e[7]);
            __syncwarp();
        }
        rowsum += __shfl_xor_sync(~0u, rowsum, 1);
        if ((lane & 1) == 0)
            psums_sm[(wm0 + mt * 16 + (lane >> 1)) * 4 + wng] = rowsum;
    }
    __syncthreads();
    if (tid < 128) {
        float s = psums_sm[tid * 4 + 0] + psums_sm[tid * 4 + 1]
                + psums_sm[tid * 4 + 2] + psums_sm[tid * 4 + 3];
        psum[((size_t)(bh * NQT + bm) * 128 + tid) * NQT + bn] = s;
    }
}

// ==================================================================
// attnv_norm: per (qt, bh) CTA 128q x 64d, double-buffered.
//  il = 1/rowsum; stream E chunks, write P = E*il in place, O += P@V.
// ==================================================================
__global__ void __launch_bounds__(256, 2) attnv_norm(float* __restrict__ attn,
                                                     const float* __restrict__ V,
                                                     const float* __restrict__ psum,
                                                     float* __restrict__ Oh) {
    const int qt = (NQT - 1) - blockIdx.x;   // big tiles first
    const int bh = blockIdx.y;
    extern __shared__ __align__(16) float smem[];
    float* As = smem;                        // 2 * 128*LDA
    float* Vs = As + 2 * 128 * LDA;          // 2 * 32*LDV
    float* stage = Vs + 2 * 32 * LDV;        // 8*272
    float* ilrow = stage + 8 * 272;          // 128

    const int tid = threadIdx.x, wid = tid >> 5, lane = tid & 31;
    const int wm0 = (wid & 3) * 32, wn0 = (wid >> 2) * 32;
    float* a = attn + ((size_t)bh * SEQ + qt * 128) * SEQ;
    const float* v = V + (size_t)bh * SEQ * HDIM;

    if (tid < 128) {
        const float* ps = psum + ((size_t)(bh * NQT + qt) * 128 + tid) * NQT;
        float s = 0.f;
        for (int t = 0; t <= qt; t++) s += ps[t];
        ilrow[tid] = 1.0f / s;
    }
    __syncthreads();

    FragC acc[2][2];
    #pragma unroll
    for (int mt = 0; mt < 2; mt++)
        #pragma unroll
        for (int nt = 0; nt < 2; nt++) wmma::fill_fragment(acc[mt][nt], 0.0f);

    const int NCH = (qt + 1) * 4;            // 32-col chunks

    float4 re[4], rv[2];
    // initial load (kc = 0)
    #pragma unroll
    for (int l = 0; l < 4; l++) {
        int vv = tid + l * 256;
        int i = vv >> 3, j = (vv & 7) * 4;
        re[l] = *reinterpret_cast<const float4*>(a + (size_t)i * SEQ + j);
    }
    #pragma unroll
    for (int l = 0; l < 2; l++) {
        int vv = tid + l * 256;
        int i = vv >> 4, j = (vv & 15) * 4;
        rv[l] = *reinterpret_cast<const float4*>(v + (size_t)i * HDIM + j);
    }
    // process chunk 0 into buf 0
    #pragma unroll
    for (int l = 0; l < 4; l++) {
        int vv = tid + l * 256;
        int i = vv >> 3, j = (vv & 7) * 4;
        float il = ilrow[i];
        float4 t = re[l];
        t.x *= il; t.y *= il; t.z *= il; t.w *= il;
        *reinterpret_cast<float4*>(a + (size_t)i * SEQ + j) = t;
        *reinterpret_cast<float4*>(&As[i * LDA + j]) =
            make_float4(f2tf32f(t.x), f2tf32f(t.y), f2tf32f(t.z), f2tf32f(t.w));
    }
    #pragma unroll
    for (int l = 0; l < 2; l++) {
        int vv = tid + l * 256;
        int i = vv >> 4, j = (vv & 15) * 4;
        float4 t = rv[l];
        *reinterpret_cast<float4*>(&Vs[i * LDV + j]) =
            make_float4(f2tf32f(t.x), f2tf32f(t.y), f2tf32f(t.z), f2tf32f(t.w));
    }
    __syncthreads();

    for (int c = 0; c < NCH; c++) {
        const int buf = c & 1;
        const bool nxt = (c + 1 < NCH);
        if (nxt) {
            const int kc = (c + 1) * 32;
            #pragma unroll
            for (int l = 0; l < 4; l++) {
                int vv = tid + l * 256;
                int i = vv >> 3, j = (vv & 7) * 4;
                re[l] = *reinterpret_cast<const float4*>(a + (size_t)i * SEQ + kc + j);
            }
            #pragma unroll
            for (int l = 0; l < 2; l++) {
                int vv = tid + l * 256;
                int i = vv >> 4, j = (vv & 15) * 4;
                rv[l] = *reinterpret_cast<const float4*>(v + (size_t)(kc + i) * HDIM + j);
            }
        }
        const float* Ab = As + buf * 128 * LDA;
        const float* Vb = Vs + buf * 32 * LDV;
        #pragma unroll
        for (int ks = 0; ks < 32; ks += 8) {
            FragA af[2];
            FragBr bf[2];
            #pragma unroll
            for (int mt = 0; mt < 2; mt++)
                wmma::load_matrix_sync(af[mt], &Ab[(wm0 + mt * 16) * LDA + ks], LDA);
            #pragma unroll
            for (int nt = 0; nt < 2; nt++)
                wmma::load_matrix_sync(bf[nt], &Vb[ks * LDV + wn0 + nt * 16], LDV);
            #pragma unroll
            for (int mt = 0; mt < 2; mt++)
                #pragma unroll
                for (int nt = 0; nt < 2; nt++)
                    wmma::mma_sync(acc[mt][nt], af[mt], bf[nt], acc[mt][nt]);
        }
        if (nxt) {
            const int kc = (c + 1) * 32;
            float* An = As + (buf ^ 1) * 128 * LDA;
            float* Vn = Vs + (buf ^ 1) * 32 * LDV;
            #pragma unroll
            for (int l = 0; l < 4; l++) {
                int vv = tid + l * 256;
                int i = vv >> 3, j = (vv & 7) * 4;
                float il = ilrow[i];
                float4 t = re[l];
                t.x *= il; t.y *= il; t.z *= il; t.w *= il;
                *reinterpret_cast<float4*>(a + (size_t)i * SEQ + kc + j) = t;
                *reinterpret_cast<float4*>(&An[i * LDA + j]) =
                    make_float4(f2tf32f(t.x), f2tf32f(t.y), f2tf32f(t.z), f2tf32f(t.w));
            }
            #pragma unroll
            for (int l = 0; l < 2; l++) {
                int vv = tid + l * 256;
                int i = vv >> 4, j = (vv & 15) * 4;
                float4 t = rv[l];
                *reinterpret_cast<float4*>(&Vn[i * LDV + j]) =
                    make_float4(f2tf32f(t.x), f2tf32f(t.y), f2tf32f(t.z), f2tf32f(t.w));
            }
        }
        __syncthreads();
    }

    // O store
    float* st = stage + wid * 272;
    #pragma unroll
    for (int mt = 0; mt < 2; mt++) {
        #pragma unroll
        for (int nt = 0; nt < 2; nt++) {
            wmma::store_matrix_sync(st, acc[mt][nt], 16, wmma::mem_row_major);
            __syncwarp();
            int r = lane >> 1, c8 = (lane & 1) * 8;
            int gq = qt * 128 + wm0 + mt * 16 + r;
            int d0 = wn0 + nt * 16 + c8;
            float out[8];
            #pragma unroll
            for (int jj = 0; jj < 8; jj++)
                out[jj] = st[r * 16 + c8 + jj];
            float* dst = Oh + (((size_t)bh * SEQ + gq) << 6) + d0;
            *reinterpret_cast<float4*>(dst)     = make_float4(out[0], out[1], out[2], out[3]);
            *reinterpret_cast<float4*>(dst + 4) = make_float4(out[4], out[5], out[6], out[7]);
            __syncwarp();
        }
    }
}

// ==================================================================
// outproj: out = Oh(gather head layout) @ Wo^T + bo, row-major out.
// Double-buffered like proj3.
// ==================================================================
__global__ void __launch_bounds__(256, 2) outproj_wmma(const float* __restrict__ Xh,
                                                       const float* __restrict__ W,
                                                       const float* __restrict__ bias,
                                                       float* __restrict__ Y) {
    extern __shared__ __align__(16) float smem[];
    float* As = smem;
    float* Bs = As + 2 * 128 * LDA;
    float* stage = Bs + 2 * 128 * LDA;

    const int tid = threadIdx.x, wid = tid >> 5, lane = tid & 31;
    const int bm = blockIdx.y, bn = blockIdx.x;
    const int wm0 = (wid & 1) * 64, wn0 = (wid >> 1) * 32;

    FragC acc[4][2];
    #pragma unroll
    for (int mt = 0; mt < 4; mt++)
        #pragma unroll
        for (int nt = 0; nt < 2; nt++) wmma::fill_fragment(acc[mt][nt], 0.0f);

    auto ldx = [&](int kc, int i, int j) -> float4 {
        int gm = bm * 128 + i;
        int b = gm >> 11, s = gm & 2047;
        int h = kc >> 6, d0 = (kc & 63) + j;
        return *reinterpret_cast<const float4*>(
            Xh + ((((size_t)b * HEADS + h) * SEQ + s) << 6) + d0);
    };

    float4 ra[4], rb[4];
    #pragma unroll
    for (int l = 0; l < 4; l++) {
        int v = tid + l * 256;
        int i = v >> 3, j = (v & 7) * 4;
        ra[l] = ldx(0, i, j);
        rb[l] = *reinterpret_cast<const float4*>(W + (size_t)(bn * 128 + i) * 1024 + j);
    }
    #pragma unroll
    for (int l = 0; l < 4; l++) {
        int v = tid + l * 256;
        int i = v >> 3, j = (v & 7) * 4;
        float4 t = ra[l], w = rb[l];
        *reinterpret_cast<float4*>(&As[i * LDA + j]) =
            make_float4(f2tf32f(t.x), f2tf32f(t.y), f2tf32f(t.z), f2tf32f(t.w));
        *reinterpret_cast<float4*>(&Bs[i * LDA + j]) =
            make_float4(f2tf32f(w.x), f2tf32f(w.y), f2tf32f(w.z), f2tf32f(w.w));
    }
    __syncthreads();

    for (int c = 0; c < 32; c++) {
        const int buf = c & 1;
        const bool nxt = (c + 1 < 32);
        if (nxt) {
            const int kc = (c + 1) * 32;
            #pragma unroll
            for (int l = 0; l < 4; l++) {
                int v = tid + l * 256;
                int i = v >> 3, j = (v & 7) * 4;
                ra[l] = ldx(kc, i, j);
                rb[l] = *reinterpret_cast<const float4*>(W + (size_t)(bn * 128 + i) * 1024 + kc + j);
            }
        }
        const float* Ab = As + buf * 128 * LDA;
        const float* Bb = Bs + buf * 128 * LDA;
        #pragma unroll
        for (int ks = 0; ks < 32; ks += 8) {
            FragA af[4];
            FragBc bf[2];
            #pragma unroll
            for (int mt = 0; mt < 4; mt++)
                wmma::load_matrix_sync(af[mt], &Ab[(wm0 + mt * 16) * LDA + ks], LDA);
            #pragma unroll
            for (int nt = 0; nt < 2; nt++)
                wmma::load_matrix_sync(bf[nt], &Bb[(wn0 + nt * 16) * LDA + ks], LDA);
            #pragma unroll
            for (int mt = 0; mt < 4; mt++)
                #pragma unroll
                for (int nt = 0; nt < 2; nt++)
                    wmma::mma_sync(acc[mt][nt], af[mt], bf[nt], acc[mt][nt]);
        }
        if (nxt) {
            float* An = As + (buf ^ 1) * 128 * LDA;
            float* Bn = Bs + (buf ^ 1) * 128 * LDA;
            #pragma unroll
            for (int l = 0; l < 4; l++) {
                int v = tid + l * 256;
                int i = v >> 3, j = (v & 7) * 4;
                float4 t = ra[l], w = rb[l];
                *reinterpret_cast<float4*>(&An[i * LDA + j]) =
                    make_float4(f2tf32f(t.x), f2tf32f(t.y), f2tf32f(t.z), f2tf32f(t.w));
                *reinterpret_cast<float4*>(&Bn[i * LDA + j]) =
                    make_float4(f2tf32f(w.x), f2tf32f(w.y), f2tf32f(w.z), f2tf32f(w.w));
            }
        }
        __syncthreads();
    }

    float* st = stage + wid * 272;
    #pragma unroll
    for (int mt = 0; mt < 4; mt++) {
        #pragma unroll
        for (int nt = 0; nt < 2; nt++) {
            wmma::store_matrix_sync(st, acc[mt][nt], 16, wmma::mem_row_major);
            __syncwarp();
            int r = lane >> 1, c8 = (lane & 1) * 8;
            int gm = bm * 128 + wm0 + mt * 16 + r;
            int gn_t = bn * 128 + wn0 + nt * 16;
            float out[8];
            #pragma unroll
            for (int jj = 0; jj < 8; jj++)
                out[jj] = st[r * 16 + c8 + jj] + bias[gn_t + c8 + jj];
            float* dst = Y + (size_t)gm * SIZE + gn_t + c8;
            *reinterpret_cast<float4*>(dst)     = make_float4(out[0], out[1], out[2], out[3]);
            *reinterpret_cast<float4*>(dst + 4) = make_float4(out[4], out[5], out[6], out[7]);
            __syncwarp();
        }
    }
}

// ==================================================================
// host launcher
// ==================================================================
extern "C" void kernel_launch(void* const* d_in, const int* in_sizes, int n_in,
                              void* d_out, int out_size) {
    const float* key   = (const float*)d_in[0];
    const float* value = (const float*)d_in[1];
    const float* query = (const float*)d_in[2];
    const float* Wk = (const float*)d_in[4];
    const float* bk = (const float*)d_in[5];
    const float* Wv = (const float*)d_in[6];
    const float* bv = (const float*)d_in[7];
    const float* Wq = (const float*)d_in[8];
    const float* bq = (const float*)d_in[9];
    const float* Wo = (const float*)d_in[10];
    const float* bo = (const float*)d_in[11];

    float *qh, *kh, *vh, *oh, *psum, *attn_scr, *out_scr;
    cudaGetSymbolAddress((void**)&qh, g_q);
    cudaGetSymbolAddress((void**)&kh, g_k);
    cudaGetSymbolAddress((void**)&vh, g_v);
    cudaGetSymbolAddress((void**)&oh, g_oh);
    cudaGetSymbolAddress((void**)&psum, g_psum);
    cudaGetSymbolAddress((void**)&attn_scr, g_attn_scratch);
    cudaGetSymbolAddress((void**)&out_scr, g_out_scratch);

    const long long OUT_ELE  = (long long)M_TOK * SIZE;
    const long long ATTN_ELE = (long long)BH * SEQ * SEQ;

    float* dout = (float*)d_out;
    float* outp;
    float* attnp;
    if ((long long)out_size >= OUT_ELE + ATTN_ELE) {
        outp = dout; attnp = dout + OUT_ELE;
    } else if ((long long)out_size == ATTN_ELE) {
        attnp = dout; outp = out_scr;
    } else {
        outp = dout; attnp = attn_scr;
    }

    cudaFuncSetAttribute(proj3_wmma,  cudaFuncAttributeMaxDynamicSharedMemorySize, SMEM_PROJ);
    cudaFuncSetAttribute(scores_exp,  cudaFuncAttributeMaxDynamicSharedMemorySize, SMEM_SCORES);
    cudaFuncSetAttribute(attnv_norm,  cudaFuncAttributeMaxDynamicSharedMemorySize, SMEM_ATTNV);
    cudaFuncSetAttribute(outproj_wmma, cudaFuncAttributeMaxDynamicSharedMemorySize, SMEM_PROJ);

    dim3 thr(256);

    dim3 gProj3(SIZE / 128, M_TOK / 128, 3);        // (8, 32, 3)
    proj3_wmma<<<gProj3, thr, SMEM_PROJ>>>(query, key, value,
                                           Wq, Wk, Wv,
                                           bq, bk, bv,
                                           qh, kh, vh);

    dim3 gScores(NQT, NQT, BH);                     // (16, 16, 32)
    scores_exp<<<gScores, thr, SMEM_SCORES>>>(qh, kh, attnp, psum);

    dim3 gAV(NQT, BH);                              // (16, 32)
    attnv_norm<<<gAV, thr, SMEM_ATTNV>>>(attnp, vh, psum, oh);

    dim3 gOut(SIZE / 128, M_TOK / 128);             // (8, 32)
    outproj_wmma<<<gOut, thr, SMEM_PROJ>>>(oh, Wo, bo, outp);
}

// round 11
// speedup vs baseline: 2.1422x; 1.0750x over previous
#include <cuda_runtime.h>
#include <mma.h>
#include <cstdint>
#include <math.h>

using namespace nvcuda;

// Problem constants
#define BATCH 2
#define SEQ   2048
#define SIZE  1024
#define HEADS 16
#define HDIM  64
#define M_TOK (BATCH * SEQ)
#define BH    (BATCH * HEADS)
#define NQT   (SEQ / 128)     // 16 q-tiles

// -------- scratch (device globals; no allocations allowed) --------
__device__ float g_q[(size_t)BH * SEQ * HDIM];        // [bh, s, d]
__device__ float g_k[(size_t)BH * SEQ * HDIM];        // [bh, s, d]
__device__ float g_v[(size_t)BH * SEQ * HDIM];        // [bh, s, d]
__device__ float g_oh[(size_t)BH * SEQ * HDIM];       // [bh, s, d]
__device__ float g_psum[(size_t)BH * SEQ * NQT];      // per-row, per-k-tile exp sums
__device__ float g_attn_scratch[(size_t)BH * SEQ * SEQ];
__device__ float g_out_scratch[(size_t)M_TOK * SIZE];

__device__ __forceinline__ float f2tf32f(float x) {
    uint32_t r;
    asm("cvt.rna.tf32.f32 %0, %1;" : "=r"(r) : "f"(x));
    return __uint_as_float(r);
}

typedef wmma::fragment<wmma::matrix_a, 16, 16, 8, wmma::precision::tf32, wmma::row_major> FragA;
typedef wmma::fragment<wmma::matrix_b, 16, 16, 8, wmma::precision::tf32, wmma::col_major> FragBc;
typedef wmma::fragment<wmma::matrix_b, 16, 16, 8, wmma::precision::tf32, wmma::row_major> FragBr;
typedef wmma::fragment<wmma::accumulator, 16, 16, 8, float> FragC;

#define LDA 36   // smem leading dim for 32-wide K tiles (pad 4)
#define LDQ 68   // smem leading dim for 64-wide tiles (pad 4)
#define LDV 68

// dynamic smem sizes (bytes)
#define SMEM_GEMM   ((2*128*LDA*2 + 4*272) * 4)              // 78080 (4-warp GEMM)
#define SMEM_SCORES ((2*128*LDQ + 8*272 + 128*4) * 4)        // 80384
#define SMEM_ATTNV  ((2*128*LDA + 2*32*LDV + 8*272 + 128)*4) // 63488

// ==================================================================
// 4-warp GEMM core: CTA 128x128, warp tile 64x64 (2x2 warps, 4x4 frags),
// BK=32, register-prefetch double buffering. 16 MMA per 8 frag-loads.
// IN_MODE: 0 = row-major X[.,1024]; 1 = gather head layout [bh,s,d]
// OUT_MODE: 0 = row-major Y; 1 = head layout
// ==================================================================
template<int IN_MODE, int OUT_MODE>
__device__ __forceinline__ void gemm_core(const float* __restrict__ X,
                                          const float* __restrict__ W,
                                          const float* __restrict__ bias,
                                          float* __restrict__ Y,
                                          int bm, int bn, float* smem) {
    float* As = smem;                       // 2 * 128*LDA
    float* Bs = As + 2 * 128 * LDA;
    float* stage = Bs + 2 * 128 * LDA;      // 4 * 272

    const int tid = threadIdx.x, wid = tid >> 5, lane = tid & 31;
    const int wm0 = (wid & 1) * 64, wn0 = (wid >> 1) * 64;

    FragC acc[4][4];
    #pragma unroll
    for (int mt = 0; mt < 4; mt++)
        #pragma unroll
        for (int nt = 0; nt < 4; nt++) wmma::fill_fragment(acc[mt][nt], 0.0f);

    auto ldx = [&](int kc, int i, int j) -> float4 {
        if (IN_MODE == 0) {
            return *reinterpret_cast<const float4*>(
                X + (size_t)(bm * 128 + i) * 1024 + kc + j);
        } else {
            int gm = bm * 128 + i;
            int b = gm >> 11, s = gm & 2047;
            int h = kc >> 6, d0 = (kc & 63) + j;
            return *reinterpret_cast<const float4*>(
                X + ((((size_t)b * HEADS + h) * SEQ + s) << 6) + d0);
        }
    };

    float4 ra[8], rb[8];
    // initial load (kc = 0): 128x32 A and B, 8 float4 each per thread
    #pragma unroll
    for (int l = 0; l < 8; l++) {
        int v = tid + l * 128;
        int i = v >> 3, j = (v & 7) * 4;
        ra[l] = ldx(0, i, j);
        rb[l] = *reinterpret_cast<const float4*>(W + (size_t)(bn * 128 + i) * 1024 + j);
    }
    #pragma unroll
    for (int l = 0; l < 8; l++) {
        int v = tid + l * 128;
        int i = v >> 3, j = (v & 7) * 4;
        float4 t = ra[l], w = rb[l];
        *reinterpret_cast<float4*>(&As[i * LDA + j]) =
            make_float4(f2tf32f(t.x), f2tf32f(t.y), f2tf32f(t.z), f2tf32f(t.w));
        *reinterpret_cast<float4*>(&Bs[i * LDA + j]) =
            make_float4(f2tf32f(w.x), f2tf32f(w.y), f2tf32f(w.z), f2tf32f(w.w));
    }
    __syncthreads();

    for (int c = 0; c < 32; c++) {
        const int buf = c & 1;
        const bool nxt = (c + 1 < 32);
        if (nxt) {
            const int kc = (c + 1) * 32;
            #pragma unroll
            for (int l = 0; l < 8; l++) {
                int v = tid + l * 128;
                int i = v >> 3, j = (v & 7) * 4;
                ra[l] = ldx(kc, i, j);
                rb[l] = *reinterpret_cast<const float4*>(W + (size_t)(bn * 128 + i) * 1024 + kc + j);
            }
        }
        const float* Ab = As + buf * 128 * LDA;
        const float* Bb = Bs + buf * 128 * LDA;
        #pragma unroll
        for (int ks = 0; ks < 32; ks += 8) {
            FragA af[4];
            FragBc bf[4];
            #pragma unroll
            for (int mt = 0; mt < 4; mt++)
                wmma::load_matrix_sync(af[mt], &Ab[(wm0 + mt * 16) * LDA + ks], LDA);
            #pragma unroll
            for (int nt = 0; nt < 4; nt++)
                wmma::load_matrix_sync(bf[nt], &Bb[(wn0 + nt * 16) * LDA + ks], LDA);
            #pragma unroll
            for (int mt = 0; mt < 4; mt++)
                #pragma unroll
                for (int nt = 0; nt < 4; nt++)
                    wmma::mma_sync(acc[mt][nt], af[mt], bf[nt], acc[mt][nt]);
        }
        if (nxt) {
            float* An = As + (buf ^ 1) * 128 * LDA;
            float* Bn = Bs + (buf ^ 1) * 128 * LDA;
            #pragma unroll
            for (int l = 0; l < 8; l++) {
                int v = tid + l * 128;
                int i = v >> 3, j = (v & 7) * 4;
                float4 t = ra[l], w = rb[l];
                *reinterpret_cast<float4*>(&An[i * LDA + j]) =
                    make_float4(f2tf32f(t.x), f2tf32f(t.y), f2tf32f(t.z), f2tf32f(t.w));
                *reinterpret_cast<float4*>(&Bn[i * LDA + j]) =
                    make_float4(f2tf32f(w.x), f2tf32f(w.y), f2tf32f(w.z), f2tf32f(w.w));
            }
        }
        __syncthreads();
    }

    // epilogue
    float* st = stage + wid * 272;
    #pragma unroll
    for (int mt = 0; mt < 4; mt++) {
        #pragma unroll
        for (int nt = 0; nt < 4; nt++) {
            wmma::store_matrix_sync(st, acc[mt][nt], 16, wmma::mem_row_major);
            __syncwarp();
            int r = lane >> 1, c8 = (lane & 1) * 8;
            int gm = bm * 128 + wm0 + mt * 16 + r;
            int gn_t = bn * 128 + wn0 + nt * 16;
            float out[8];
            #pragma unroll
            for (int jj = 0; jj < 8; jj++)
                out[jj] = st[r * 16 + c8 + jj] + bias[gn_t + c8 + jj];
            float* dst;
            if (OUT_MODE == 0) {
                dst = Y + (size_t)gm * SIZE + gn_t + c8;
            } else {
                int b = gm >> 11, s = gm & 2047;
                int h = gn_t >> 6, d0 = (gn_t & 63) + c8;
                dst = Y + ((((size_t)b * HEADS + h) * SEQ + s) << 6) + d0;
            }
            *reinterpret_cast<float4*>(dst)     = make_float4(out[0], out[1], out[2], out[3]);
            *reinterpret_cast<float4*>(dst + 4) = make_float4(out[4], out[5], out[6], out[7]);
            __syncwarp();
        }
    }
}

// proj3: z selects q/k/v; output to head layout.
__global__ void __launch_bounds__(128, 2) proj3_wmma(
    const float* __restrict__ X0, const float* __restrict__ X1, const float* __restrict__ X2,
    const float* __restrict__ W0, const float* __restrict__ W1, const float* __restrict__ W2,
    const float* __restrict__ b0, const float* __restrict__ b1, const float* __restrict__ b2,
    float* __restrict__ Y0, float* __restrict__ Y1, float* __restrict__ Y2) {
    extern __shared__ __align__(16) float smem[];
    const int z = blockIdx.z;
    const float* X = (z == 0) ? X0 : (z == 1) ? X1 : X2;
    const float* W = (z == 0) ? W0 : (z == 1) ? W1 : W2;
    const float* bias = (z == 0) ? b0 : (z == 1) ? b1 : b2;
    float* Y = (z == 0) ? Y0 : (z == 1) ? Y1 : Y2;
    gemm_core<0, 1>(X, W, bias, Y, blockIdx.y, blockIdx.x, smem);
}

// outproj: gather from head layout, row-major out.
__global__ void __launch_bounds__(128, 2) outproj_wmma(const float* __restrict__ Xh,
                                                       const float* __restrict__ W,
                                                       const float* __restrict__ bias,
                                                       float* __restrict__ Y) {
    extern __shared__ __align__(16) float smem[];
    gemm_core<1, 0>(Xh, W, bias, Y, blockIdx.y, blockIdx.x, smem);
}

// ==================================================================
// scores_exp: E = exp((Q.K^T)/8) with causal mask; single smem load
// (K=64 entirely resident). Upper-tri CTAs write zeros. Row partial
// sums -> g_psum.
// ==================================================================
__global__ void __launch_bounds__(256, 2) scores_exp(const float* __restrict__ Q,
                                                     const float* __restrict__ Kh,
                                                     float* __restrict__ attn,
                                                     float* __restrict__ psum) {
    const int bn = blockIdx.x, bm = blockIdx.y, bh = blockIdx.z;
    const int tid = threadIdx.x;

    if (bn > bm) {
        const float4 z4 = {0.f, 0.f, 0.f, 0.f};
        float* base = attn + ((size_t)bh * SEQ + bm * 128) * SEQ + bn * 128;
        #pragma unroll
        for (int l = 0; l < 16; l++) {
            int idx = tid + l * 256;        // 0..4095
            int i = idx >> 5, j4 = idx & 31;
            *reinterpret_cast<float4*>(base + (size_t)i * SEQ + j4 * 4) = z4;
        }
        return;
    }

    extern __shared__ __align__(16) float smem[];
    float* Qs = smem;                      // 128*LDQ
    float* Ks = Qs + 128 * LDQ;            // 128*LDQ
    float* stage = Ks + 128 * LDQ;         // 8*272
    float* psums_sm = stage + 8 * 272;     // 128*4

    const int wid = tid >> 5, lane = tid & 31;
    const int wm0 = (wid & 1) * 64, wng = wid >> 1;
    const int wn0 = wng * 32;
    const float* q = Q + (size_t)bh * SEQ * HDIM;
    const float* k = Kh + (size_t)bh * SEQ * HDIM;
    const bool diag = (bm == bn);

    #pragma unroll
    for (int l = 0; l < 8; l++) {
        int f4 = tid + l * 256;
        int i = f4 >> 4, j = (f4 & 15) * 4;
        float4 t = *reinterpret_cast<const float4*>(q + (size_t)(bm * 128 + i) * HDIM + j);
        *reinterpret_cast<float4*>(&Qs[i * LDQ + j]) =
            make_float4(f2tf32f(t.x), f2tf32f(t.y), f2tf32f(t.z), f2tf32f(t.w));
        float4 w = *reinterpret_cast<const float4*>(k + (size_t)(bn * 128 + i) * HDIM + j);
        *reinterpret_cast<float4*>(&Ks[i * LDQ + j]) =
            make_float4(f2tf32f(w.x), f2tf32f(w.y), f2tf32f(w.z), f2tf32f(w.w));
    }
    __syncthreads();

    FragC acc[4][2];
    #pragma unroll
    for (int mt = 0; mt < 4; mt++)
        #pragma unroll
        for (int nt = 0; nt < 2; nt++) wmma::fill_fragment(acc[mt][nt], 0.0f);

    #pragma unroll
    for (int ks = 0; ks < 64; ks += 8) {
        FragA af[4];
        FragBc bf[2];
        #pragma unroll
        for (int mt = 0; mt < 4; mt++)
            wmma::load_matrix_sync(af[mt], &Qs[(wm0 + mt * 16) * LDQ + ks], LDQ);
        #pragma unroll
        for (int nt = 0; nt < 2; nt++)
            wmma::load_matrix_sync(bf[nt], &Ks[(wn0 + nt * 16) * LDQ + ks], LDQ);
        #pragma unroll
        for (int mt = 0; mt < 4; mt++)
            #pragma unroll
            for (int nt = 0; nt < 2; nt++)
                wmma::mma_sync(acc[mt][nt], af[mt], bf[nt], acc[mt][nt]);
    }

    float* st = stage + wid * 272;
    #pragma unroll
    for (int mt = 0; mt < 4; mt++) {
        float rowsum = 0.f;
        #pragma unroll
        for (int nt = 0; nt < 2; nt++) {
            wmma::store_matrix_sync(st, acc[mt][nt], 16, wmma::mem_row_major);
            __syncwarp();
            int r = lane >> 1, c8 = (lane & 1) * 8;
            int gq = bm * 128 + wm0 + mt * 16 + r;
            int gk0 = bn * 128 + wn0 + nt * 16 + c8;
            float e[8];
            #pragma unroll
            for (int jj = 0; jj < 8; jj++) {
                float s = st[r * 16 + c8 + jj] * 0.125f;
                float v = __expf(s);
                if (diag && (gk0 + jj > gq)) v = 0.f;
                e[jj] = v;
                rowsum += v;
            }
            float* dst = attn + ((size_t)bh * SEQ + gq) * SEQ + gk0;
            *reinterpret_cast<float4*>(dst)     = make_float4(e[0], e[1], e[2], e[3]);
            *reinterpret_cast<float4*>(dst + 4) = make_float4(e[4], e[5], e[6], e[7]);
            __syncwarp();
        }
        rowsum += __shfl_xor_sync(~0u, rowsum, 1);
        if ((lane & 1) == 0)
            psums_sm[(wm0 + mt * 16 + (lane >> 1)) * 4 + wng] = rowsum;
    }
    __syncthreads();
    if (tid < 128) {
        float s = psums_sm[tid * 4 + 0] + psums_sm[tid * 4 + 1]
                + psums_sm[tid * 4 + 2] + psums_sm[tid * 4 + 3];
        psum[((size_t)(bh * NQT + bm) * 128 + tid) * NQT + bn] = s;
    }
}

// ==================================================================
// attnv_norm: per (qt, bh) CTA 128q x 64d, double-buffered.
//  il = 1/rowsum; stream E chunks, write P = E*il in place, O += P@V.
// ==================================================================
__global__ void __launch_bounds__(256, 2) attnv_norm(float* __restrict__ attn,
                                                     const float* __restrict__ V,
                                                     const float* __restrict__ psum,
                                                     float* __restrict__ Oh) {
    const int qt = (NQT - 1) - blockIdx.x;   // big tiles first
    const int bh = blockIdx.y;
    extern __shared__ __align__(16) float smem[];
    float* As = smem;                        // 2 * 128*LDA
    float* Vs = As + 2 * 128 * LDA;          // 2 * 32*LDV
    float* stage = Vs + 2 * 32 * LDV;        // 8*272
    float* ilrow = stage + 8 * 272;          // 128

    const int tid = threadIdx.x, wid = tid >> 5, lane = tid & 31;
    const int wm0 = (wid & 3) * 32, wn0 = (wid >> 2) * 32;
    float* a = attn + ((size_t)bh * SEQ + qt * 128) * SEQ;
    const float* v = V + (size_t)bh * SEQ * HDIM;

    if (tid < 128) {
        const float* ps = psum + ((size_t)(bh * NQT + qt) * 128 + tid) * NQT;
        float s = 0.f;
        for (int t = 0; t <= qt; t++) s += ps[t];
        ilrow[tid] = 1.0f / s;
    }
    __syncthreads();

    FragC acc[2][2];
    #pragma unroll
    for (int mt = 0; mt < 2; mt++)
        #pragma unroll
        for (int nt = 0; nt < 2; nt++) wmma::fill_fragment(acc[mt][nt], 0.0f);

    const int NCH = (qt + 1) * 4;            // 32-col chunks

    float4 re[4], rv[2];
    #pragma unroll
    for (int l = 0; l < 4; l++) {
        int vv = tid + l * 256;
        int i = vv >> 3, j = (vv & 7) * 4;
        re[l] = *reinterpret_cast<const float4*>(a + (size_t)i * SEQ + j);
    }
    #pragma unroll
    for (int l = 0; l < 2; l++) {
        int vv = tid + l * 256;
        int i = vv >> 4, j = (vv & 15) * 4;
        rv[l] = *reinterpret_cast<const float4*>(v + (size_t)i * HDIM + j);
    }
    #pragma unroll
    for (int l = 0; l < 4; l++) {
        int vv = tid + l * 256;
        int i = vv >> 3, j = (vv & 7) * 4;
        float il = ilrow[i];
        float4 t = re[l];
        t.x *= il; t.y *= il; t.z *= il; t.w *= il;
        *reinterpret_cast<float4*>(a + (size_t)i * SEQ + j) = t;
        *reinterpret_cast<float4*>(&As[i * LDA + j]) =
            make_float4(f2tf32f(t.x), f2tf32f(t.y), f2tf32f(t.z), f2tf32f(t.w));
    }
    #pragma unroll
    for (int l = 0; l < 2; l++) {
        int vv = tid + l * 256;
        int i = vv >> 4, j = (vv & 15) * 4;
        float4 t = rv[l];
        *reinterpret_cast<float4*>(&Vs[i * LDV + j]) =
            make_float4(f2tf32f(t.x), f2tf32f(t.y), f2tf32f(t.z), f2tf32f(t.w));
    }
    __syncthreads();

    for (int c = 0; c < NCH; c++) {
        const int buf = c & 1;
        const bool nxt = (c + 1 < NCH);
        if (nxt) {
            const int kc = (c + 1) * 32;
            #pragma unroll
            for (int l = 0; l < 4; l++) {
                int vv = tid + l * 256;
                int i = vv >> 3, j = (vv & 7) * 4;
                re[l] = *reinterpret_cast<const float4*>(a + (size_t)i * SEQ + kc + j);
            }
            #pragma unroll
            for (int l = 0; l < 2; l++) {
                int vv = tid + l * 256;
                int i = vv >> 4, j = (vv & 15) * 4;
                rv[l] = *reinterpret_cast<const float4*>(v + (size_t)(kc + i) * HDIM + j);
            }
        }
        const float* Ab = As + buf * 128 * LDA;
        const float* Vb = Vs + buf * 32 * LDV;
        #pragma unroll
        for (int ks = 0; ks < 32; ks += 8) {
            FragA af[2];
            FragBr bf[2];
            #pragma unroll
            for (int mt = 0; mt < 2; mt++)
                wmma::load_matrix_sync(af[mt], &Ab[(wm0 + mt * 16) * LDA + ks], LDA);
            #pragma unroll
            for (int nt = 0; nt < 2; nt++)
                wmma::load_matrix_sync(bf[nt], &Vb[ks * LDV + wn0 + nt * 16], LDV);
            #pragma unroll
            for (int mt = 0; mt < 2; mt++)
                #pragma unroll
                for (int nt = 0; nt < 2; nt++)
                    wmma::mma_sync(acc[mt][nt], af[mt], bf[nt], acc[mt][nt]);
        }
        if (nxt) {
            const int kc = (c + 1) * 32;
            float* An = As + (buf ^ 1) * 128 * LDA;
            float* Vn = Vs + (buf ^ 1) * 32 * LDV;
            #pragma unroll
            for (int l = 0; l < 4; l++) {
                int vv = tid + l * 256;
                int i = vv >> 3, j = (vv & 7) * 4;
                float il = ilrow[i];
                float4 t = re[l];
                t.x *= il; t.y *= il; t.z *= il; t.w *= il;
                *reinterpret_cast<float4*>(a + (size_t)i * SEQ + kc + j) = t;
                *reinterpret_cast<float4*>(&An[i * LDA + j]) =
                    make_float4(f2tf32f(t.x), f2tf32f(t.y), f2tf32f(t.z), f2tf32f(t.w));
            }
            #pragma unroll
            for (int l = 0; l < 2; l++) {
                int vv = tid + l * 256;
                int i = vv >> 4, j = (vv & 15) * 4;
                float4 t = rv[l];
                *reinterpret_cast<float4*>(&Vn[i * LDV + j]) =
                    make_float4(f2tf32f(t.x), f2tf32f(t.y), f2tf32f(t.z), f2tf32f(t.w));
            }
        }
        __syncthreads();
    }

    float* st = stage + wid * 272;
    #pragma unroll
    for (int mt = 0; mt < 2; mt++) {
        #pragma unroll
        for (int nt = 0; nt < 2; nt++) {
            wmma::store_matrix_sync(st, acc[mt][nt], 16, wmma::mem_row_major);
            __syncwarp();
            int r = lane >> 1, c8 = (lane & 1) * 8;
            int gq = qt * 128 + wm0 + mt * 16 + r;
            int d0 = wn0 + nt * 16 + c8;
            float out[8];
            #pragma unroll
            for (int jj = 0; jj < 8; jj++)
                out[jj] = st[r * 16 + c8 + jj];
            float* dst = Oh + (((size_t)bh * SEQ + gq) << 6) + d0;
            *reinterpret_cast<float4*>(dst)     = make_float4(out[0], out[1], out[2], out[3]);
            *reinterpret_cast<float4*>(dst + 4) = make_float4(out[4], out[5], out[6], out[7]);
            __syncwarp();
        }
    }
}

// ==================================================================
// host launcher
// ==================================================================
extern "C" void kernel_launch(void* const* d_in, const int* in_sizes, int n_in,
                              void* d_out, int out_size) {
    const float* key   = (const float*)d_in[0];
    const float* value = (const float*)d_in[1];
    const float* query = (const float*)d_in[2];
    const float* Wk = (const float*)d_in[4];
    const float* bk = (const float*)d_in[5];
    const float* Wv = (const float*)d_in[6];
    const float* bv = (const float*)d_in[7];
    const float* Wq = (const float*)d_in[8];
    const float* bq = (const float*)d_in[9];
    const float* Wo = (const float*)d_in[10];
    const float* bo = (const float*)d_in[11];

    float *qh, *kh, *vh, *oh, *psum, *attn_scr, *out_scr;
    cudaGetSymbolAddress((void**)&qh, g_q);
    cudaGetSymbolAddress((void**)&kh, g_k);
    cudaGetSymbolAddress((void**)&vh, g_v);
    cudaGetSymbolAddress((void**)&oh, g_oh);
    cudaGetSymbolAddress((void**)&psum, g_psum);
    cudaGetSymbolAddress((void**)&attn_scr, g_attn_scratch);
    cudaGetSymbolAddress((void**)&out_scr, g_out_scratch);

    const long long OUT_ELE  = (long long)M_TOK * SIZE;
    const long long ATTN_ELE = (long long)BH * SEQ * SEQ;

    float* dout = (float*)d_out;
    float* outp;
    float* attnp;
    if ((long long)out_size >= OUT_ELE + ATTN_ELE) {
        outp = dout; attnp = dout + OUT_ELE;
    } else if ((long long)out_size == ATTN_ELE) {
        attnp = dout; outp = out_scr;
    } else {
        outp = dout; attnp = attn_scr;
    }

    cudaFuncSetAttribute(proj3_wmma,   cudaFuncAttributeMaxDynamicSharedMemorySize, SMEM_GEMM);
    cudaFuncSetAttribute(outproj_wmma, cudaFuncAttributeMaxDynamicSharedMemorySize, SMEM_GEMM);
    cudaFuncSetAttribute(scores_exp,   cudaFuncAttributeMaxDynamicSharedMemorySize, SMEM_SCORES);
    cudaFuncSetAttribute(attnv_norm,   cudaFuncAttributeMaxDynamicSharedMemorySize, SMEM_ATTNV);

    dim3 thrG(128);
    dim3 thr(256);

    dim3 gProj3(SIZE / 128, M_TOK / 128, 3);        // (8, 32, 3)
    proj3_wmma<<<gProj3, thrG, SMEM_GEMM>>>(query, key, value,
                                            Wq, Wk, Wv,
                                            bq, bk, bv,
                                            qh, kh, vh);

    dim3 gScores(NQT, NQT, BH);                     // (16, 16, 32)
    scores_exp<<<gScores, thr, SMEM_SCORES>>>(qh, kh, attnp, psum);

    dim3 gAV(NQT, BH);                              // (16, 32)
    attnv_norm<<<gAV, thr, SMEM_ATTNV>>>(attnp, vh, psum, oh);

    dim3 gOut(SIZE / 128, M_TOK / 128);             // (8, 32)
    outproj_wmma<<<gOut, thrG, SMEM_GEMM>>>(oh, Wo, bo, outp);
}